// round 4
// baseline (speedup 1.0000x reference)
#include <cuda_runtime.h>
#include <stdint.h>
#include <math.h>

#define BB 32
#define TXX 384
#define TYY 1536
#define DIMK 256
#define NF 80
#define NEGF (-1000000000.0f)
#define CONSTF (-73.51508265637381f)   /* -0.5*log(2*pi)*80 */

#define ATTN_SZ ((size_t)BB * TXX * TYY)

// DP pipeline depth
#define DSLOT 16
#define PF 14

// ---------------- scratch (static device memory; no allocation) -------------
__device__ float g_xp[(size_t)BB * NF * TXX];          // [b][f][t]
__device__ float g_xsq[BB * TXX];
__device__ float g_ysq[BB * TYY];
__device__ float g_v[(size_t)BB * TYY * TXX];          // [b][y][t]
__device__ int   g_idx[BB * TYY];
__device__ float g_dur[BB * TXX];

// ---------------------------------------------------------------------------
__device__ __forceinline__ void cp16(uint32_t s, const void* g) {
    asm volatile("cp.async.cg.shared.global [%0], [%1], 16;\n" :: "r"(s), "l"(g));
}

// ---------------------------------------------------------------------------
// y_square[b][s] = -0.5 * sum_f y[b][f][s]^2
__global__ void ysq_kernel(const float* __restrict__ y) {
    int b = blockIdx.y;
    int s = blockIdx.x * 256 + threadIdx.x;
    if (s >= TYY) return;
    const float* yb = y + (size_t)b * NF * TYY + s;
    float sum = 0.f;
#pragma unroll
    for (int f = 0; f < NF; ++f) {
        float v = yb[(size_t)f * TYY];
        sum += v * v;
    }
    g_ysq[b * TYY + s] = -0.5f * sum;
}

// ---------------------------------------------------------------------------
// xp[b][f][t] = sum_d x[b][t][d] * W[f][d] + bias[f];  xsq[b][t] = -0.5*sum_f xp^2
__global__ __launch_bounds__(160) void xp_kernel(const float* __restrict__ x,
                                                 const float* __restrict__ W,
                                                 const float* __restrict__ bias) {
    __shared__ float xs[32][128];   // [k][t]
    __shared__ float ws[32][80];    // [k][f]
    __shared__ float part[10][128];

    int b  = blockIdx.y;
    int t0 = blockIdx.x * 128;
    int tid = threadIdx.x;
    int tx = tid & 15;        // t-group
    int fg = tid >> 4;        // f-group (0..9)

    float acc[8][8];
#pragma unroll
    for (int i = 0; i < 8; ++i)
#pragma unroll
        for (int j = 0; j < 8; ++j) acc[i][j] = 0.f;

    const float* xb = x + ((size_t)b * TXX + t0) * DIMK;

    for (int k0 = 0; k0 < DIMK; k0 += 32) {
        for (int i = tid; i < 1024; i += 160) {     // 128 t x 8 float4
            int t = i >> 3, kq = i & 7;
            float4 v = *(const float4*)(xb + (size_t)t * DIMK + k0 + kq * 4);
            xs[kq * 4 + 0][t] = v.x; xs[kq * 4 + 1][t] = v.y;
            xs[kq * 4 + 2][t] = v.z; xs[kq * 4 + 3][t] = v.w;
        }
        for (int i = tid; i < 640; i += 160) {      // 80 f x 8 float4
            int f = i >> 3, kq = i & 7;
            float4 v = *(const float4*)(W + (size_t)f * DIMK + k0 + kq * 4);
            ws[kq * 4 + 0][f] = v.x; ws[kq * 4 + 1][f] = v.y;
            ws[kq * 4 + 2][f] = v.z; ws[kq * 4 + 3][f] = v.w;
        }
        __syncthreads();
#pragma unroll 8
        for (int kk = 0; kk < 32; ++kk) {
            float4 xa = *(const float4*)&xs[kk][tx * 8];
            float4 xb4 = *(const float4*)&xs[kk][tx * 8 + 4];
            float4 wa = *(const float4*)&ws[kk][fg * 8];
            float4 wb4 = *(const float4*)&ws[kk][fg * 8 + 4];
            float xv[8] = {xa.x, xa.y, xa.z, xa.w, xb4.x, xb4.y, xb4.z, xb4.w};
            float wv[8] = {wa.x, wa.y, wa.z, wa.w, wb4.x, wb4.y, wb4.z, wb4.w};
#pragma unroll
            for (int i = 0; i < 8; ++i)
#pragma unroll
                for (int j = 0; j < 8; ++j) acc[i][j] += xv[i] * wv[j];
        }
        __syncthreads();
    }

    float bv[8];
#pragma unroll
    for (int j = 0; j < 8; ++j) bv[j] = bias[fg * 8 + j];

    float ss[8];
#pragma unroll
    for (int i = 0; i < 8; ++i) ss[i] = 0.f;

#pragma unroll
    for (int i = 0; i < 8; ++i) {
        int t = t0 + tx * 8 + i;
#pragma unroll
        for (int j = 0; j < 8; ++j) {
            float v = acc[i][j] + bv[j];
            g_xp[((size_t)b * NF + fg * 8 + j) * TXX + t] = v;
            ss[i] += v * v;
        }
    }
#pragma unroll
    for (int i = 0; i < 8; ++i) part[fg][tx * 8 + i] = ss[i];
    __syncthreads();
    if (tid < 128) {
        float s = 0.f;
#pragma unroll
        for (int g = 0; g < 10; ++g) s += part[g][tid];
        g_xsq[b * TXX + t0 + tid] = -0.5f * s;
    }
}

// ---------------------------------------------------------------------------
// v[b][y][t] = ysq[y] + sum_f xp[b][f][t]*y[b][f][y] + xsq[t] + CONST  (masked)
__global__ __launch_bounds__(256) void cross_kernel(const float* __restrict__ y,
                                                    const int* __restrict__ xl,
                                                    const int* __restrict__ yl) {
    extern __shared__ float sm[];
    float* Ys = sm;            // [80][128]
    float* Xs = sm + 80 * 128; // [80][128]

    int b  = blockIdx.z;
    int y0 = blockIdx.y * 128;
    int t0 = blockIdx.x * 128;
    int ylen = yl[b], xlen = xl[b];
    if (y0 >= ylen) return;

    int tid = threadIdx.x;

    // Fast path: whole t-tile masked -> write NEGF, skip GEMM.
    if (t0 >= xlen) {
        int ymax = y0 + 128; if (ymax > ylen) ymax = ylen;
        int nrow = ymax - y0;
        float4 negv = make_float4(NEGF, NEGF, NEGF, NEGF);
        for (int i = tid; i < nrow * 32; i += 256) {
            int yg = y0 + (i >> 5);
            int qd = i & 31;
            *(float4*)(g_v + ((size_t)b * TYY + yg) * TXX + t0 + qd * 4) = negv;
        }
        return;
    }

    const float* yb = y + (size_t)b * NF * TYY;
    for (int i = tid; i < 2560; i += 256) {
        int f = i >> 5, q = i & 31;
        *(float4*)&Ys[f * 128 + q * 4] =
            *(const float4*)(yb + (size_t)f * TYY + y0 + q * 4);
    }
    const float* xpb = g_xp + (size_t)b * NF * TXX;
    for (int i = tid; i < 2560; i += 256) {
        int f = i >> 5, q = i & 31;
        *(float4*)&Xs[f * 128 + q * 4] =
            *(const float4*)(xpb + (size_t)f * TXX + t0 + q * 4);
    }
    __syncthreads();

    int tx = tid & 15;   // t
    int ty = tid >> 4;   // y

    float acc[8][8];
#pragma unroll
    for (int i = 0; i < 8; ++i)
#pragma unroll
        for (int j = 0; j < 8; ++j) acc[i][j] = 0.f;

#pragma unroll 4
    for (int f = 0; f < NF; ++f) {
        float4 ya = *(const float4*)&Ys[f * 128 + ty * 8];
        float4 yb4 = *(const float4*)&Ys[f * 128 + ty * 8 + 4];
        float4 xa = *(const float4*)&Xs[f * 128 + tx * 8];
        float4 xb4 = *(const float4*)&Xs[f * 128 + tx * 8 + 4];
        float yv[8] = {ya.x, ya.y, ya.z, ya.w, yb4.x, yb4.y, yb4.z, yb4.w};
        float xv[8] = {xa.x, xa.y, xa.z, xa.w, xb4.x, xb4.y, xb4.z, xb4.w};
#pragma unroll
        for (int i = 0; i < 8; ++i)
#pragma unroll
            for (int j = 0; j < 8; ++j) acc[i][j] += yv[i] * xv[j];
    }

    int tbase = t0 + tx * 8;
    float xsqv[8];
#pragma unroll
    for (int j = 0; j < 8; ++j) xsqv[j] = g_xsq[b * TXX + tbase + j];

#pragma unroll
    for (int i = 0; i < 8; ++i) {
        int yg = y0 + ty * 8 + i;
        if (yg >= ylen) continue;
        float ysv = g_ysq[b * TYY + yg];
        float ov[8];
#pragma unroll
        for (int j = 0; j < 8; ++j) {
            float val = ((ysv + acc[i][j]) + xsqv[j]) + CONSTF;
            ov[j] = (tbase + j < xlen) ? val : NEGF;
        }
        float* vout = g_v + ((size_t)b * TYY + yg) * TXX + tbase;
        *(float4*)(vout + 0) = make_float4(ov[0], ov[1], ov[2], ov[3]);
        *(float4*)(vout + 4) = make_float4(ov[4], ov[5], ov[6], ov[7]);
    }
}

// ---------------------------------------------------------------------------
// DP forward + backtrack.  One warp per batch.  Lane L owns t = 12L + j.
// Forward: cp.async ring (depth PF) + register double-buffer of the next row
// (LDS issued one iteration early) + early carry-shfl.
// Backtrack: warp-cooperative 8-row prefetch of decision words, shfl-distributed.
__global__ __launch_bounds__(32) void dp_kernel(const int* __restrict__ xl,
                                                const int* __restrict__ yl) {
    extern __shared__ float smf[];
    float* ring = smf;                                       // [DSLOT][TXX]
    unsigned short* sdec = (unsigned short*)(smf + DSLOT * TXX);  // [TYY][32]

    int b = blockIdx.x;
    int lane = threadIdx.x;
    int ylen = yl[b], xlen = xl[b];

    const float* vb = g_v + (size_t)b * TYY * TXX;
    uint32_t ring_base = (uint32_t)__cvta_generic_to_shared(ring);
    uint32_t lane_off = (uint32_t)(lane * 12 * 4);  // bytes within a row

    // Prologue: prefetch rows 0..PF-1 (one commit group per row)
#pragma unroll
    for (int r = 0; r < PF; ++r) {
        uint32_t s = ring_base + (uint32_t)(r * TXX * 4) + lane_off;
        const float* g = vb + (size_t)r * TXX + lane * 12;
        cp16(s, g); cp16(s + 16, g + 4); cp16(s + 32, g + 8);
        asm volatile("cp.async.commit_group;\n" ::: "memory");
    }
    // row 0 landed (<=PF-1 groups outstanding)
    asm volatile("cp.async.wait_group %0;\n" :: "n"(PF - 1) : "memory");

    float4 c0, c1, c2;
    {
        const float4* rp = (const float4*)(ring + lane * 12);
        c0 = rp[0]; c1 = rp[1]; c2 = rp[2];
    }

    float q[12];
#pragma unroll
    for (int j = 0; j < 12; ++j) q[j] = NEGF;
    if (lane == 0) q[0] = 0.0f;

    for (int yy = 0; yy < ylen; ++yy) {
        // issue prefetch of row yy+PF into slot (yy+PF)%DSLOT
        {
            int pr = yy + PF; if (pr > TYY - 1) pr = TYY - 1;
            uint32_t slot = (uint32_t)((yy + PF) & (DSLOT - 1));
            uint32_t s = ring_base + slot * (uint32_t)(TXX * 4) + lane_off;
            const float* g = vb + (size_t)pr * TXX + lane * 12;
            cp16(s, g); cp16(s + 16, g + 4); cp16(s + 32, g + 8);
            asm volatile("cp.async.commit_group;\n" ::: "memory");
        }
        // carry shfl issued early (uses q[11] from previous row)
        float carry = __shfl_up_sync(0xffffffffu, q[11], 1);
        if (lane == 0) carry = NEGF;

        // wait for row yy+1, load it into the double buffer
        asm volatile("cp.async.wait_group %0;\n" :: "n"(PF - 1) : "memory");
        int ns = (yy + 1) & (DSLOT - 1);
        const float4* rp = (const float4*)(ring + ns * TXX + lane * 12);
        float4 n0 = rp[0], n1 = rp[1], n2 = rp[2];

        float vv[12] = {c0.x, c0.y, c0.z, c0.w,
                        c1.x, c1.y, c1.z, c1.w,
                        c2.x, c2.y, c2.z, c2.w};
        unsigned bits = 0u;
#pragma unroll
        for (int j = 11; j >= 1; --j)
            bits |= ((q[j] < q[j - 1]) ? 1u : 0u) << j;
        bits |= (q[0] < carry) ? 1u : 0u;
#pragma unroll
        for (int j = 11; j >= 1; --j)
            q[j] = vv[j] + fmaxf(q[j], q[j - 1]);
        q[0] = vv[0] + fmaxf(q[0], carry);

        sdec[yy * 32 + lane] = (unsigned short)bits;
        c0 = n0; c1 = n1; c2 = n2;
    }
    asm volatile("cp.async.wait_all;\n" ::: "memory");
    __syncwarp();

#pragma unroll
    for (int j = 0; j < 12; ++j) g_dur[b * TXX + lane * 12 + j] = 0.0f;
    __syncwarp();

    // --------- cooperative backtrack (all lanes mirror scalar state) --------
    int idx = xlen - 1;
    int w = idx / 12, r = idx - w * 12;
    int cnt = 0;
    int* gi = g_idx + b * TYY;
    int yy = ylen - 1;
    while (yy >= 0) {
        int w0 = w;
        // lanes 0..7 load rows yy..yy-7 at word w0; lanes 8..15 at word w0-1
        int k8 = lane & 7;
        int rowk = yy - k8;
        int wc = (lane < 8) ? w0 : (w0 > 0 ? w0 - 1 : 0);
        unsigned wordl = 0u;
        if (lane < 16 && rowk >= 0) wordl = (unsigned)sdec[rowk * 32 + wc];

        int nsteps = (yy >= 7) ? 8 : (yy + 1);
        for (int k = 0; k < nsteps; ++k) {
            unsigned ww  = __shfl_sync(0xffffffffu, wordl, k);
            unsigned ww1 = __shfl_sync(0xffffffffu, wordl, k + 8);
            unsigned use = (w == w0) ? ww : ww1;
            int row = yy - k;
            bool move = (idx != 0) && (row > 0) &&
                        ((idx == row) || (((use >> r) & 1u) != 0u));
            if (lane == 0) gi[row] = idx;
            cnt++;
            if (move) {
                if (lane == 0) g_dur[b * TXX + idx] = (float)cnt;
                cnt = 0; idx--;
                if (--r < 0) { r = 11; w--; }
            }
        }
        yy -= nsteps;
    }
    if (lane == 0) g_dur[b * TXX + idx] = (float)cnt;
}

// ---------------------------------------------------------------------------
// attn[b][t][s] = (s < ylen && g_idx[b][s] == t) ? 1 : 0
__global__ __launch_bounds__(128) void attn_kernel(const int* __restrict__ yl,
                                                   float* __restrict__ out) {
    int b = blockIdx.y;
    int t = blockIdx.x;
    int tid = threadIdx.x;
    int ylen = yl[b];
    const int* gi = g_idx + b * TYY;
    float* o = out + ((size_t)b * TXX + t) * TYY;
#pragma unroll
    for (int it = 0; it < 3; ++it) {
        int s4 = tid + it * 128;
        int s = s4 * 4;
        int4 iv = *(const int4*)(gi + s);
        float4 ov;
        ov.x = (s + 0 < ylen && iv.x == t) ? 1.f : 0.f;
        ov.y = (s + 1 < ylen && iv.y == t) ? 1.f : 0.f;
        ov.z = (s + 2 < ylen && iv.z == t) ? 1.f : 0.f;
        ov.w = (s + 3 < ylen && iv.w == t) ? 1.f : 0.f;
        *(float4*)(o + s) = ov;
    }
}

// ---------------------------------------------------------------------------
// loss + durations tail
__global__ __launch_bounds__(256) void loss_kernel(const float* __restrict__ pred,
                                                   const int* __restrict__ xl,
                                                   float* __restrict__ out,
                                                   int write_tail) {
    __shared__ float red[256];
    int tid = threadIdx.x;
    float s = 0.f;
    for (int i = tid; i < BB * TXX; i += 256) {
        int b = i / TXX, t = i - b * TXX;
        float dur = g_dur[i];
        float tl = (t < xl[b]) ? logf(dur + 1e-8f) : 0.0f;
        float d = pred[i] - tl;
        s += d * d;
        if (write_tail) out[ATTN_SZ + 1 + i] = dur;
    }
    red[tid] = s;
    __syncthreads();
    for (int off = 128; off > 0; off >>= 1) {
        if (tid < off) red[tid] += red[tid + off];
        __syncthreads();
    }
    if (tid == 0 && write_tail) {
        int sx = 0;
        for (int bb2 = 0; bb2 < BB; ++bb2) sx += xl[bb2];
        out[ATTN_SZ] = red[0] / (float)sx;
    }
}

// ---------------------------------------------------------------------------
extern "C" void kernel_launch(void* const* d_in, const int* in_sizes, int n_in,
                              void* d_out, int out_size) {
    const float* x    = (const float*)d_in[0];
    const float* y    = (const float*)d_in[1];
    const int*   xlen = (const int*)d_in[4];
    const int*   ylen = (const int*)d_in[5];
    const float* pred = (const float*)d_in[6];
    const float* W    = (const float*)d_in[7];
    const float* bias = (const float*)d_in[8];
    float* out = (float*)d_out;

    int dp_smem = DSLOT * TXX * (int)sizeof(float) + TYY * 32 * (int)sizeof(unsigned short);

    cudaFuncSetAttribute(cross_kernel, cudaFuncAttributeMaxDynamicSharedMemorySize,
                         2 * 80 * 128 * (int)sizeof(float));
    cudaFuncSetAttribute(dp_kernel, cudaFuncAttributeMaxDynamicSharedMemorySize,
                         dp_smem);

    ysq_kernel<<<dim3(TYY / 256, BB), 256>>>(y);
    xp_kernel<<<dim3(TXX / 128, BB), 160>>>(x, W, bias);
    cross_kernel<<<dim3(TXX / 128, TYY / 128, BB), 256,
                   2 * 80 * 128 * sizeof(float)>>>(y, xlen, ylen);
    dp_kernel<<<BB, 32, dp_smem>>>(xlen, ylen);
    attn_kernel<<<dim3(TXX, BB), 128>>>(ylen, out);

    int write_tail = ((size_t)out_size >= ATTN_SZ + 1 + BB * TXX) ? 1 : 0;
    loss_kernel<<<1, 256>>>(pred, xlen, out, write_tail);
}

// round 5
// speedup vs baseline: 1.2338x; 1.2338x over previous
#include <cuda_runtime.h>
#include <stdint.h>
#include <math.h>

#define BB 32
#define TXX 384
#define TYY 1536
#define DIMK 256
#define NF 80
#define NEGF (-1000000000.0f)
#define CONSTF (-73.51508265637381f)   /* -0.5*log(2*pi)*80 */

#define ATTN_SZ ((size_t)BB * TXX * TYY)

// DP ring: 16 rows = 4 blocks of 4 rows; 3 blocks in flight
#define DSLOT 16

// ---------------- scratch (static device memory; no allocation) -------------
__device__ float g_xp[(size_t)BB * NF * TXX];          // [b][f][t]
__device__ float g_xsq[BB * TXX];
__device__ float g_ysq[BB * TYY];
__device__ float g_v[(size_t)BB * TYY * TXX];          // [b][y][t]
__device__ int   g_idx[BB * TYY];
__device__ float g_dur[BB * TXX];

// ---------------------------------------------------------------------------
__device__ __forceinline__ void cp16(uint32_t s, const void* g) {
    asm volatile("cp.async.cg.shared.global [%0], [%1], 16;\n" :: "r"(s), "l"(g));
}

// ---------------------------------------------------------------------------
// y_square[b][s] = -0.5 * sum_f y[b][f][s]^2
__global__ void ysq_kernel(const float* __restrict__ y) {
    int b = blockIdx.y;
    int s = blockIdx.x * 256 + threadIdx.x;
    if (s >= TYY) return;
    const float* yb = y + (size_t)b * NF * TYY + s;
    float sum = 0.f;
#pragma unroll
    for (int f = 0; f < NF; ++f) {
        float v = yb[(size_t)f * TYY];
        sum += v * v;
    }
    g_ysq[b * TYY + s] = -0.5f * sum;
}

// ---------------------------------------------------------------------------
// xp[b][f][t] = sum_d x[b][t][d] * W[f][d] + bias[f];  xsq[b][t] = -0.5*sum_f xp^2
__global__ __launch_bounds__(160) void xp_kernel(const float* __restrict__ x,
                                                 const float* __restrict__ W,
                                                 const float* __restrict__ bias) {
    __shared__ float xs[32][128];   // [k][t]
    __shared__ float ws[32][80];    // [k][f]
    __shared__ float part[10][128];

    int b  = blockIdx.y;
    int t0 = blockIdx.x * 128;
    int tid = threadIdx.x;
    int tx = tid & 15;        // t-group
    int fg = tid >> 4;        // f-group (0..9)

    float acc[8][8];
#pragma unroll
    for (int i = 0; i < 8; ++i)
#pragma unroll
        for (int j = 0; j < 8; ++j) acc[i][j] = 0.f;

    const float* xb = x + ((size_t)b * TXX + t0) * DIMK;

    for (int k0 = 0; k0 < DIMK; k0 += 32) {
        for (int i = tid; i < 1024; i += 160) {     // 128 t x 8 float4
            int t = i >> 3, kq = i & 7;
            float4 v = *(const float4*)(xb + (size_t)t * DIMK + k0 + kq * 4);
            xs[kq * 4 + 0][t] = v.x; xs[kq * 4 + 1][t] = v.y;
            xs[kq * 4 + 2][t] = v.z; xs[kq * 4 + 3][t] = v.w;
        }
        for (int i = tid; i < 640; i += 160) {      // 80 f x 8 float4
            int f = i >> 3, kq = i & 7;
            float4 v = *(const float4*)(W + (size_t)f * DIMK + k0 + kq * 4);
            ws[kq * 4 + 0][f] = v.x; ws[kq * 4 + 1][f] = v.y;
            ws[kq * 4 + 2][f] = v.z; ws[kq * 4 + 3][f] = v.w;
        }
        __syncthreads();
#pragma unroll 8
        for (int kk = 0; kk < 32; ++kk) {
            float4 xa = *(const float4*)&xs[kk][tx * 8];
            float4 xb4 = *(const float4*)&xs[kk][tx * 8 + 4];
            float4 wa = *(const float4*)&ws[kk][fg * 8];
            float4 wb4 = *(const float4*)&ws[kk][fg * 8 + 4];
            float xv[8] = {xa.x, xa.y, xa.z, xa.w, xb4.x, xb4.y, xb4.z, xb4.w};
            float wv[8] = {wa.x, wa.y, wa.z, wa.w, wb4.x, wb4.y, wb4.z, wb4.w};
#pragma unroll
            for (int i = 0; i < 8; ++i)
#pragma unroll
                for (int j = 0; j < 8; ++j) acc[i][j] += xv[i] * wv[j];
        }
        __syncthreads();
    }

    float bv[8];
#pragma unroll
    for (int j = 0; j < 8; ++j) bv[j] = bias[fg * 8 + j];

    float ss[8];
#pragma unroll
    for (int i = 0; i < 8; ++i) ss[i] = 0.f;

#pragma unroll
    for (int i = 0; i < 8; ++i) {
        int t = t0 + tx * 8 + i;
#pragma unroll
        for (int j = 0; j < 8; ++j) {
            float v = acc[i][j] + bv[j];
            g_xp[((size_t)b * NF + fg * 8 + j) * TXX + t] = v;
            ss[i] += v * v;
        }
    }
#pragma unroll
    for (int i = 0; i < 8; ++i) part[fg][tx * 8 + i] = ss[i];
    __syncthreads();
    if (tid < 128) {
        float s = 0.f;
#pragma unroll
        for (int g = 0; g < 10; ++g) s += part[g][tid];
        g_xsq[b * TXX + t0 + tid] = -0.5f * s;
    }
}

// ---------------------------------------------------------------------------
// v[b][y][t] = ysq[y] + sum_f xp[b][f][t]*y[b][f][y] + xsq[t] + CONST  (masked)
__global__ __launch_bounds__(256) void cross_kernel(const float* __restrict__ y,
                                                    const int* __restrict__ xl,
                                                    const int* __restrict__ yl) {
    extern __shared__ float sm[];
    float* Ys = sm;            // [80][128]
    float* Xs = sm + 80 * 128; // [80][128]

    int b  = blockIdx.z;
    int y0 = blockIdx.y * 128;
    int t0 = blockIdx.x * 128;
    int ylen = yl[b], xlen = xl[b];
    if (y0 >= ylen) return;

    int tid = threadIdx.x;

    // Fast path: whole t-tile masked -> write NEGF, skip GEMM.
    if (t0 >= xlen) {
        int ymax = y0 + 128; if (ymax > ylen) ymax = ylen;
        int nrow = ymax - y0;
        float4 negv = make_float4(NEGF, NEGF, NEGF, NEGF);
        for (int i = tid; i < nrow * 32; i += 256) {
            int yg = y0 + (i >> 5);
            int qd = i & 31;
            *(float4*)(g_v + ((size_t)b * TYY + yg) * TXX + t0 + qd * 4) = negv;
        }
        return;
    }

    const float* yb = y + (size_t)b * NF * TYY;
    for (int i = tid; i < 2560; i += 256) {
        int f = i >> 5, q = i & 31;
        *(float4*)&Ys[f * 128 + q * 4] =
            *(const float4*)(yb + (size_t)f * TYY + y0 + q * 4);
    }
    const float* xpb = g_xp + (size_t)b * NF * TXX;
    for (int i = tid; i < 2560; i += 256) {
        int f = i >> 5, q = i & 31;
        *(float4*)&Xs[f * 128 + q * 4] =
            *(const float4*)(xpb + (size_t)f * TXX + t0 + q * 4);
    }
    __syncthreads();

    int tx = tid & 15;   // t
    int ty = tid >> 4;   // y

    float acc[8][8];
#pragma unroll
    for (int i = 0; i < 8; ++i)
#pragma unroll
        for (int j = 0; j < 8; ++j) acc[i][j] = 0.f;

#pragma unroll 4
    for (int f = 0; f < NF; ++f) {
        float4 ya = *(const float4*)&Ys[f * 128 + ty * 8];
        float4 yb4 = *(const float4*)&Ys[f * 128 + ty * 8 + 4];
        float4 xa = *(const float4*)&Xs[f * 128 + tx * 8];
        float4 xb4 = *(const float4*)&Xs[f * 128 + tx * 8 + 4];
        float yv[8] = {ya.x, ya.y, ya.z, ya.w, yb4.x, yb4.y, yb4.z, yb4.w};
        float xv[8] = {xa.x, xa.y, xa.z, xa.w, xb4.x, xb4.y, xb4.z, xb4.w};
#pragma unroll
        for (int i = 0; i < 8; ++i)
#pragma unroll
            for (int j = 0; j < 8; ++j) acc[i][j] += yv[i] * xv[j];
    }

    int tbase = t0 + tx * 8;
    float xsqv[8];
#pragma unroll
    for (int j = 0; j < 8; ++j) xsqv[j] = g_xsq[b * TXX + tbase + j];

#pragma unroll
    for (int i = 0; i < 8; ++i) {
        int yg = y0 + ty * 8 + i;
        if (yg >= ylen) continue;
        float ysv = g_ysq[b * TYY + yg];
        float ov[8];
#pragma unroll
        for (int j = 0; j < 8; ++j) {
            float val = ((ysv + acc[i][j]) + xsqv[j]) + CONSTF;
            ov[j] = (tbase + j < xlen) ? val : NEGF;
        }
        float* vout = g_v + ((size_t)b * TYY + yg) * TXX + tbase;
        *(float4*)(vout + 0) = make_float4(ov[0], ov[1], ov[2], ov[3]);
        *(float4*)(vout + 4) = make_float4(ov[4], ov[5], ov[6], ov[7]);
    }
}

// ---------------------------------------------------------------------------
// DP forward + backtrack.  One warp per batch.  Lane L owns t = 12L + j.
// Forward: 4 rows per cp.async commit group, ONE wait per 4 rows (amortizes
// the wait/commit overhead 4x).  Backtrack: lane-0 scalar control with 8-row
// batched register loads of decision words (MLP hides LDS latency).
__global__ __launch_bounds__(32) void dp_kernel(const int* __restrict__ xl,
                                                const int* __restrict__ yl) {
    extern __shared__ float smf[];
    float* ring = smf;                                       // [DSLOT][TXX]
    unsigned short* sdec = (unsigned short*)(smf + DSLOT * TXX);  // [TYY][32]

    int b = blockIdx.x;
    int lane = threadIdx.x;
    int ylen = yl[b], xlen = xl[b];

    const float* vb = g_v + (size_t)b * TYY * TXX;
    uint32_t ring_base = (uint32_t)__cvta_generic_to_shared(ring);
    uint32_t lane_off = (uint32_t)(lane * 12 * 4);  // bytes within a row

    // Prologue: 3 blocks (rows 0..11), one commit group per 4-row block
#pragma unroll
    for (int blk = 0; blk < 3; ++blk) {
#pragma unroll
        for (int k = 0; k < 4; ++k) {
            int row = blk * 4 + k;
            uint32_t s = ring_base + (uint32_t)(row * TXX * 4) + lane_off;
            const float* g = vb + (size_t)row * TXX + lane * 12;
            cp16(s, g); cp16(s + 16, g + 4); cp16(s + 32, g + 8);
        }
        asm volatile("cp.async.commit_group;\n" ::: "memory");
    }

    float q[12];
#pragma unroll
    for (int j = 0; j < 12; ++j) q[j] = NEGF;
    if (lane == 0) q[0] = 0.0f;

    for (int yb = 0; yb < ylen; yb += 4) {
        // prefetch block rows yb+12 .. yb+15 (skip rows >= ylen)
#pragma unroll
        for (int k = 0; k < 4; ++k) {
            int row = yb + 12 + k;
            if (row < ylen) {
                uint32_t s = ring_base + (uint32_t)((row & (DSLOT - 1)) * TXX * 4) + lane_off;
                const float* g = vb + (size_t)row * TXX + lane * 12;
                cp16(s, g); cp16(s + 16, g + 4); cp16(s + 32, g + 8);
            }
        }
        asm volatile("cp.async.commit_group;\n" ::: "memory");
        // ensure block yb (oldest of <=4 outstanding) has landed
        asm volatile("cp.async.wait_group 3;\n" ::: "memory");

#pragma unroll
        for (int k = 0; k < 4; ++k) {
            int yy = yb + k;
            if (yy >= ylen) break;
            const float4* rp = (const float4*)(ring + (yy & (DSLOT - 1)) * TXX + lane * 12);
            float4 c0 = rp[0], c1 = rp[1], c2 = rp[2];

            float carry = __shfl_up_sync(0xffffffffu, q[11], 1);
            if (lane == 0) carry = NEGF;
            float vv[12] = {c0.x, c0.y, c0.z, c0.w,
                            c1.x, c1.y, c1.z, c1.w,
                            c2.x, c2.y, c2.z, c2.w};
            unsigned bits = 0u;
#pragma unroll
            for (int j = 11; j >= 1; --j)
                bits |= ((q[j] < q[j - 1]) ? 1u : 0u) << j;
            bits |= (q[0] < carry) ? 1u : 0u;
#pragma unroll
            for (int j = 11; j >= 1; --j)
                q[j] = vv[j] + fmaxf(q[j], q[j - 1]);
            q[0] = vv[0] + fmaxf(q[0], carry);

            sdec[yy * 32 + lane] = (unsigned short)bits;
        }
    }
    asm volatile("cp.async.wait_all;\n" ::: "memory");
    __syncwarp();

#pragma unroll
    for (int j = 0; j < 12; ++j) g_dur[b * TXX + lane * 12 + j] = 0.0f;
    __syncwarp();

    // --------- backtrack: lane-0 scalar, 8-row batched word loads ----------
    if (lane == 0) {
        int idx = xlen - 1;
        int w = idx / 12, r = idx - w * 12;
        int cnt = 0;
        int* gi = g_idx + b * TYY;
        int yy = ylen - 1;
        while (yy >= 0) {
            int w0 = w;
            unsigned wa[8], wb2[8];
            if (yy >= 7) {
                // batched loads: 16 independent LDS, latency overlapped
#pragma unroll
                for (int k = 0; k < 8; ++k)
                    wa[k] = (unsigned)sdec[(yy - k) * 32 + w0];
                if (w0 > 0) {
#pragma unroll
                    for (int k = 0; k < 8; ++k)
                        wb2[k] = (unsigned)sdec[(yy - k) * 32 + (w0 - 1)];
                } else {
#pragma unroll
                    for (int k = 0; k < 8; ++k) wb2[k] = 0u;
                }
#pragma unroll
                for (int k = 0; k < 8; ++k) {
                    int row = yy - k;
                    unsigned use = (w == w0) ? wa[k] : wb2[k];
                    gi[row] = idx;
                    cnt++;
                    bool move = (idx != 0) && (row > 0) &&
                                ((idx == row) || (((use >> r) & 1u) != 0u));
                    if (move) {
                        g_dur[b * TXX + idx] = (float)cnt;
                        cnt = 0; idx--;
                        if (--r < 0) { r = 11; w--; }
                    }
                }
                yy -= 8;
            } else {
                int row = yy;
                unsigned use = (unsigned)sdec[row * 32 + w];
                gi[row] = idx;
                cnt++;
                bool move = (idx != 0) && (row > 0) &&
                            ((idx == row) || (((use >> r) & 1u) != 0u));
                if (move) {
                    g_dur[b * TXX + idx] = (float)cnt;
                    cnt = 0; idx--;
                    if (--r < 0) { r = 11; w--; }
                }
                yy -= 1;
            }
        }
        g_dur[b * TXX + idx] = (float)cnt;
    }
}

// ---------------------------------------------------------------------------
// attn[b][t][s] = (s < ylen && g_idx[b][s] == t) ? 1 : 0
__global__ __launch_bounds__(128) void attn_kernel(const int* __restrict__ yl,
                                                   float* __restrict__ out) {
    int b = blockIdx.y;
    int t = blockIdx.x;
    int tid = threadIdx.x;
    int ylen = yl[b];
    const int* gi = g_idx + b * TYY;
    float* o = out + ((size_t)b * TXX + t) * TYY;
#pragma unroll
    for (int it = 0; it < 3; ++it) {
        int s4 = tid + it * 128;
        int s = s4 * 4;
        int4 iv = *(const int4*)(gi + s);
        float4 ov;
        ov.x = (s + 0 < ylen && iv.x == t) ? 1.f : 0.f;
        ov.y = (s + 1 < ylen && iv.y == t) ? 1.f : 0.f;
        ov.z = (s + 2 < ylen && iv.z == t) ? 1.f : 0.f;
        ov.w = (s + 3 < ylen && iv.w == t) ? 1.f : 0.f;
        *(float4*)(o + s) = ov;
    }
}

// ---------------------------------------------------------------------------
// loss + durations tail
__global__ __launch_bounds__(256) void loss_kernel(const float* __restrict__ pred,
                                                   const int* __restrict__ xl,
                                                   float* __restrict__ out,
                                                   int write_tail) {
    __shared__ float red[256];
    int tid = threadIdx.x;
    float s = 0.f;
    for (int i = tid; i < BB * TXX; i += 256) {
        int b = i / TXX, t = i - b * TXX;
        float dur = g_dur[i];
        float tl = (t < xl[b]) ? logf(dur + 1e-8f) : 0.0f;
        float d = pred[i] - tl;
        s += d * d;
        if (write_tail) out[ATTN_SZ + 1 + i] = dur;
    }
    red[tid] = s;
    __syncthreads();
    for (int off = 128; off > 0; off >>= 1) {
        if (tid < off) red[tid] += red[tid + off];
        __syncthreads();
    }
    if (tid == 0 && write_tail) {
        int sx = 0;
        for (int bb2 = 0; bb2 < BB; ++bb2) sx += xl[bb2];
        out[ATTN_SZ] = red[0] / (float)sx;
    }
}

// ---------------------------------------------------------------------------
extern "C" void kernel_launch(void* const* d_in, const int* in_sizes, int n_in,
                              void* d_out, int out_size) {
    const float* x    = (const float*)d_in[0];
    const float* y    = (const float*)d_in[1];
    const int*   xlen = (const int*)d_in[4];
    const int*   ylen = (const int*)d_in[5];
    const float* pred = (const float*)d_in[6];
    const float* W    = (const float*)d_in[7];
    const float* bias = (const float*)d_in[8];
    float* out = (float*)d_out;

    int dp_smem = DSLOT * TXX * (int)sizeof(float) + TYY * 32 * (int)sizeof(unsigned short);

    cudaFuncSetAttribute(cross_kernel, cudaFuncAttributeMaxDynamicSharedMemorySize,
                         2 * 80 * 128 * (int)sizeof(float));
    cudaFuncSetAttribute(dp_kernel, cudaFuncAttributeMaxDynamicSharedMemorySize,
                         dp_smem);

    ysq_kernel<<<dim3(TYY / 256, BB), 256>>>(y);
    xp_kernel<<<dim3(TXX / 128, BB), 160>>>(x, W, bias);
    cross_kernel<<<dim3(TXX / 128, TYY / 128, BB), 256,
                   2 * 80 * 128 * sizeof(float)>>>(y, xlen, ylen);
    dp_kernel<<<BB, 32, dp_smem>>>(xlen, ylen);
    attn_kernel<<<dim3(TXX, BB), 128>>>(ylen, out);

    int write_tail = ((size_t)out_size >= ATTN_SZ + 1 + BB * TXX) ? 1 : 0;
    loss_kernel<<<1, 256>>>(pred, xlen, out, write_tail);
}

// round 6
// speedup vs baseline: 1.2396x; 1.0047x over previous
#include <cuda_runtime.h>
#include <stdint.h>
#include <math.h>

#define BB 32
#define TXX 384
#define TYY 1536
#define DIMK 256
#define NF 80
#define NEGF (-1000000000.0f)
#define CONSTF (-73.51508265637381f)   /* -0.5*log(2*pi)*80 */

#define ATTN_SZ ((size_t)BB * TXX * TYY)

// DP ring: 32 rows = 4 blocks of 8 rows; 2 blocks ahead in flight
#define DSLOT 32

// ---------------- scratch (static device memory; no allocation) -------------
__device__ float g_xp[(size_t)BB * NF * TXX];          // [b][f][t]
__device__ float g_xsq[BB * TXX];
__device__ float g_ysq[BB * TYY];
__device__ float g_v[(size_t)BB * TYY * TXX];          // [b][y][t]
__device__ int   g_idx[BB * TYY];
__device__ float g_dur[BB * TXX];

// ---------------------------------------------------------------------------
__device__ __forceinline__ void cp16(uint32_t s, const void* g) {
    asm volatile("cp.async.cg.shared.global [%0], [%1], 16;\n" :: "r"(s), "l"(g));
}

// ---------------------------------------------------------------------------
// y_square[b][s] = -0.5 * sum_f y[b][f][s]^2
__global__ void ysq_kernel(const float* __restrict__ y) {
    int b = blockIdx.y;
    int s = blockIdx.x * 256 + threadIdx.x;
    if (s >= TYY) return;
    const float* yb = y + (size_t)b * NF * TYY + s;
    float sum = 0.f;
#pragma unroll
    for (int f = 0; f < NF; ++f) {
        float v = yb[(size_t)f * TYY];
        sum += v * v;
    }
    g_ysq[b * TYY + s] = -0.5f * sum;
}

// ---------------------------------------------------------------------------
// xp[b][f][t] = sum_d x[b][t][d] * W[f][d] + bias[f];  xsq[b][t] = -0.5*sum_f xp^2
__global__ __launch_bounds__(160) void xp_kernel(const float* __restrict__ x,
                                                 const float* __restrict__ W,
                                                 const float* __restrict__ bias) {
    __shared__ float xs[32][128];   // [k][t]
    __shared__ float ws[32][80];    // [k][f]
    __shared__ float part[10][128];

    int b  = blockIdx.y;
    int t0 = blockIdx.x * 128;
    int tid = threadIdx.x;
    int tx = tid & 15;        // t-group
    int fg = tid >> 4;        // f-group (0..9)

    float acc[8][8];
#pragma unroll
    for (int i = 0; i < 8; ++i)
#pragma unroll
        for (int j = 0; j < 8; ++j) acc[i][j] = 0.f;

    const float* xb = x + ((size_t)b * TXX + t0) * DIMK;

    for (int k0 = 0; k0 < DIMK; k0 += 32) {
        for (int i = tid; i < 1024; i += 160) {     // 128 t x 8 float4
            int t = i >> 3, kq = i & 7;
            float4 v = *(const float4*)(xb + (size_t)t * DIMK + k0 + kq * 4);
            xs[kq * 4 + 0][t] = v.x; xs[kq * 4 + 1][t] = v.y;
            xs[kq * 4 + 2][t] = v.z; xs[kq * 4 + 3][t] = v.w;
        }
        for (int i = tid; i < 640; i += 160) {      // 80 f x 8 float4
            int f = i >> 3, kq = i & 7;
            float4 v = *(const float4*)(W + (size_t)f * DIMK + k0 + kq * 4);
            ws[kq * 4 + 0][f] = v.x; ws[kq * 4 + 1][f] = v.y;
            ws[kq * 4 + 2][f] = v.z; ws[kq * 4 + 3][f] = v.w;
        }
        __syncthreads();
#pragma unroll 8
        for (int kk = 0; kk < 32; ++kk) {
            float4 xa = *(const float4*)&xs[kk][tx * 8];
            float4 xb4 = *(const float4*)&xs[kk][tx * 8 + 4];
            float4 wa = *(const float4*)&ws[kk][fg * 8];
            float4 wb4 = *(const float4*)&ws[kk][fg * 8 + 4];
            float xv[8] = {xa.x, xa.y, xa.z, xa.w, xb4.x, xb4.y, xb4.z, xb4.w};
            float wv[8] = {wa.x, wa.y, wa.z, wa.w, wb4.x, wb4.y, wb4.z, wb4.w};
#pragma unroll
            for (int i = 0; i < 8; ++i)
#pragma unroll
                for (int j = 0; j < 8; ++j) acc[i][j] += xv[i] * wv[j];
        }
        __syncthreads();
    }

    float bv[8];
#pragma unroll
    for (int j = 0; j < 8; ++j) bv[j] = bias[fg * 8 + j];

    float ss[8];
#pragma unroll
    for (int i = 0; i < 8; ++i) ss[i] = 0.f;

#pragma unroll
    for (int i = 0; i < 8; ++i) {
        int t = t0 + tx * 8 + i;
#pragma unroll
        for (int j = 0; j < 8; ++j) {
            float v = acc[i][j] + bv[j];
            g_xp[((size_t)b * NF + fg * 8 + j) * TXX + t] = v;
            ss[i] += v * v;
        }
    }
#pragma unroll
    for (int i = 0; i < 8; ++i) part[fg][tx * 8 + i] = ss[i];
    __syncthreads();
    if (tid < 128) {
        float s = 0.f;
#pragma unroll
        for (int g = 0; g < 10; ++g) s += part[g][tid];
        g_xsq[b * TXX + t0 + tid] = -0.5f * s;
    }
}

// ---------------------------------------------------------------------------
// v[b][y][t] = ysq[y] + sum_f xp[b][f][t]*y[b][f][y] + xsq[t] + CONST  (masked)
__global__ __launch_bounds__(256) void cross_kernel(const float* __restrict__ y,
                                                    const int* __restrict__ xl,
                                                    const int* __restrict__ yl) {
    extern __shared__ float sm[];
    float* Ys = sm;            // [80][128]
    float* Xs = sm + 80 * 128; // [80][128]

    int b  = blockIdx.z;
    int y0 = blockIdx.y * 128;
    int t0 = blockIdx.x * 128;
    int ylen = yl[b], xlen = xl[b];
    if (y0 >= ylen) return;

    int tid = threadIdx.x;

    // Fast path: whole t-tile masked -> write NEGF, skip GEMM.
    if (t0 >= xlen) {
        int ymax = y0 + 128; if (ymax > ylen) ymax = ylen;
        int nrow = ymax - y0;
        float4 negv = make_float4(NEGF, NEGF, NEGF, NEGF);
        for (int i = tid; i < nrow * 32; i += 256) {
            int yg = y0 + (i >> 5);
            int qd = i & 31;
            *(float4*)(g_v + ((size_t)b * TYY + yg) * TXX + t0 + qd * 4) = negv;
        }
        return;
    }

    const float* yb = y + (size_t)b * NF * TYY;
    for (int i = tid; i < 2560; i += 256) {
        int f = i >> 5, q = i & 31;
        *(float4*)&Ys[f * 128 + q * 4] =
            *(const float4*)(yb + (size_t)f * TYY + y0 + q * 4);
    }
    const float* xpb = g_xp + (size_t)b * NF * TXX;
    for (int i = tid; i < 2560; i += 256) {
        int f = i >> 5, q = i & 31;
        *(float4*)&Xs[f * 128 + q * 4] =
            *(const float4*)(xpb + (size_t)f * TXX + t0 + q * 4);
    }
    __syncthreads();

    int tx = tid & 15;   // t
    int ty = tid >> 4;   // y

    float acc[8][8];
#pragma unroll
    for (int i = 0; i < 8; ++i)
#pragma unroll
        for (int j = 0; j < 8; ++j) acc[i][j] = 0.f;

#pragma unroll 4
    for (int f = 0; f < NF; ++f) {
        float4 ya = *(const float4*)&Ys[f * 128 + ty * 8];
        float4 yb4 = *(const float4*)&Ys[f * 128 + ty * 8 + 4];
        float4 xa = *(const float4*)&Xs[f * 128 + tx * 8];
        float4 xb4 = *(const float4*)&Xs[f * 128 + tx * 8 + 4];
        float yv[8] = {ya.x, ya.y, ya.z, ya.w, yb4.x, yb4.y, yb4.z, yb4.w};
        float xv[8] = {xa.x, xa.y, xa.z, xa.w, xb4.x, xb4.y, xb4.z, xb4.w};
#pragma unroll
        for (int i = 0; i < 8; ++i)
#pragma unroll
            for (int j = 0; j < 8; ++j) acc[i][j] += yv[i] * xv[j];
    }

    int tbase = t0 + tx * 8;
    float xsqv[8];
#pragma unroll
    for (int j = 0; j < 8; ++j) xsqv[j] = g_xsq[b * TXX + tbase + j];

#pragma unroll
    for (int i = 0; i < 8; ++i) {
        int yg = y0 + ty * 8 + i;
        if (yg >= ylen) continue;
        float ysv = g_ysq[b * TYY + yg];
        float ov[8];
#pragma unroll
        for (int j = 0; j < 8; ++j) {
            float val = ((ysv + acc[i][j]) + xsqv[j]) + CONSTF;
            ov[j] = (tbase + j < xlen) ? val : NEGF;
        }
        float* vout = g_v + ((size_t)b * TYY + yg) * TXX + tbase;
        *(float4*)(vout + 0) = make_float4(ov[0], ov[1], ov[2], ov[3]);
        *(float4*)(vout + 4) = make_float4(ov[4], ov[5], ov[6], ov[7]);
    }
}

// ---------------------------------------------------------------------------
// DP forward + backtrack.  One warp per batch.  Lane L owns t = 12L + j.
// Forward: 8 rows per cp.async commit group (ring 32 rows), ONE wait per 8
// rows; rows register-batched 4 at a time so LDS latency is MLP-hidden; no
// per-row bounds branches (overrun rows compute garbage never consumed;
// sdec padded by 8 rows).
__global__ __launch_bounds__(32) void dp_kernel(const int* __restrict__ xl,
                                                const int* __restrict__ yl) {
    extern __shared__ float smf[];
    float* ring = smf;                                        // [DSLOT][TXX]
    unsigned short* sdec = (unsigned short*)(smf + DSLOT * TXX); // [TYY+8][32]

    int b = blockIdx.x;
    int lane = threadIdx.x;
    int ylen = yl[b], xlen = xl[b];

    const float* vb = g_v + (size_t)b * TYY * TXX;
    uint32_t ring_base = (uint32_t)__cvta_generic_to_shared(ring);
    uint32_t lane_off = (uint32_t)(lane * 12 * 4);  // bytes within a row

    // Prologue: 2 blocks (rows 0..15), one commit group per 8-row block
#pragma unroll
    for (int blk = 0; blk < 2; ++blk) {
#pragma unroll
        for (int k = 0; k < 8; ++k) {
            int row = blk * 8 + k;
            uint32_t s = ring_base + (uint32_t)(row * TXX * 4) + lane_off;
            const float* g = vb + (size_t)row * TXX + lane * 12;
            cp16(s, g); cp16(s + 16, g + 4); cp16(s + 32, g + 8);
        }
        asm volatile("cp.async.commit_group;\n" ::: "memory");
    }

    float q[12];
#pragma unroll
    for (int j = 0; j < 12; ++j) q[j] = NEGF;
    if (lane == 0) q[0] = 0.0f;

    for (int yb = 0; yb < ylen; yb += 8) {
        // prefetch block rows yb+16 .. yb+23 (clamp global row, slot unclamped)
#pragma unroll
        for (int k = 0; k < 8; ++k) {
            int rowi = yb + 16 + k;
            int rowg = (rowi > TYY - 1) ? (TYY - 1) : rowi;
            uint32_t s = ring_base + (uint32_t)((rowi & (DSLOT - 1)) * TXX * 4) + lane_off;
            const float* g = vb + (size_t)rowg * TXX + lane * 12;
            cp16(s, g); cp16(s + 16, g + 4); cp16(s + 32, g + 8);
        }
        asm volatile("cp.async.commit_group;\n" ::: "memory");
        // ensure block yb has landed (keep 2 groups outstanding)
        asm volatile("cp.async.wait_group 2;\n" ::: "memory");

        // two register-batched sub-blocks of 4 rows
#pragma unroll
        for (int h = 0; h < 2; ++h) {
            float4 r0[4], r1[4], r2[4];
#pragma unroll
            for (int k = 0; k < 4; ++k) {
                const float4* rp = (const float4*)(ring +
                    ((yb + h * 4 + k) & (DSLOT - 1)) * TXX + lane * 12);
                r0[k] = rp[0]; r1[k] = rp[1]; r2[k] = rp[2];
            }
#pragma unroll
            for (int k = 0; k < 4; ++k) {
                int yy = yb + h * 4 + k;
                float carry = __shfl_up_sync(0xffffffffu, q[11], 1);
                if (lane == 0) carry = NEGF;
                float vv[12] = {r0[k].x, r0[k].y, r0[k].z, r0[k].w,
                                r1[k].x, r1[k].y, r1[k].z, r1[k].w,
                                r2[k].x, r2[k].y, r2[k].z, r2[k].w};
                unsigned bits = 0u;
#pragma unroll
                for (int j = 11; j >= 1; --j)
                    bits |= ((q[j] < q[j - 1]) ? 1u : 0u) << j;
                bits |= (q[0] < carry) ? 1u : 0u;
#pragma unroll
                for (int j = 11; j >= 1; --j)
                    q[j] = vv[j] + fmaxf(q[j], q[j - 1]);
                q[0] = vv[0] + fmaxf(q[0], carry);
                sdec[yy * 32 + lane] = (unsigned short)bits;
            }
        }
    }
    asm volatile("cp.async.wait_all;\n" ::: "memory");
    __syncwarp();

#pragma unroll
    for (int j = 0; j < 12; ++j) g_dur[b * TXX + lane * 12 + j] = 0.0f;
    __syncwarp();

    // --------- backtrack: lane-0 scalar, 8-row batched word loads ----------
    if (lane == 0) {
        int idx = xlen - 1;
        int w = idx / 12, r = idx - w * 12;
        int cnt = 0;
        int* gi = g_idx + b * TYY;
        int yy = ylen - 1;
        while (yy >= 0) {
            int w0 = w;
            unsigned wa[8], wb2[8];
            if (yy >= 7) {
#pragma unroll
                for (int k = 0; k < 8; ++k)
                    wa[k] = (unsigned)sdec[(yy - k) * 32 + w0];
                if (w0 > 0) {
#pragma unroll
                    for (int k = 0; k < 8; ++k)
                        wb2[k] = (unsigned)sdec[(yy - k) * 32 + (w0 - 1)];
                } else {
#pragma unroll
                    for (int k = 0; k < 8; ++k) wb2[k] = 0u;
                }
#pragma unroll
                for (int k = 0; k < 8; ++k) {
                    int row = yy - k;
                    unsigned use = (w == w0) ? wa[k] : wb2[k];
                    gi[row] = idx;
                    cnt++;
                    bool move = (idx != 0) && (row > 0) &&
                                ((idx == row) || (((use >> r) & 1u) != 0u));
                    if (move) {
                        g_dur[b * TXX + idx] = (float)cnt;
                        cnt = 0; idx--;
                        if (--r < 0) { r = 11; w--; }
                    }
                }
                yy -= 8;
            } else {
                int row = yy;
                unsigned use = (unsigned)sdec[row * 32 + w];
                gi[row] = idx;
                cnt++;
                bool move = (idx != 0) && (row > 0) &&
                            ((idx == row) || (((use >> r) & 1u) != 0u));
                if (move) {
                    g_dur[b * TXX + idx] = (float)cnt;
                    cnt = 0; idx--;
                    if (--r < 0) { r = 11; w--; }
                }
                yy -= 1;
            }
        }
        g_dur[b * TXX + idx] = (float)cnt;
    }
}

// ---------------------------------------------------------------------------
// attn[b][t][s] = (s < ylen && g_idx[b][s] == t) ? 1 : 0
__global__ __launch_bounds__(128) void attn_kernel(const int* __restrict__ yl,
                                                   float* __restrict__ out) {
    int b = blockIdx.y;
    int t = blockIdx.x;
    int tid = threadIdx.x;
    int ylen = yl[b];
    const int* gi = g_idx + b * TYY;
    float* o = out + ((size_t)b * TXX + t) * TYY;
#pragma unroll
    for (int it = 0; it < 3; ++it) {
        int s4 = tid + it * 128;
        int s = s4 * 4;
        int4 iv = *(const int4*)(gi + s);
        float4 ov;
        ov.x = (s + 0 < ylen && iv.x == t) ? 1.f : 0.f;
        ov.y = (s + 1 < ylen && iv.y == t) ? 1.f : 0.f;
        ov.z = (s + 2 < ylen && iv.z == t) ? 1.f : 0.f;
        ov.w = (s + 3 < ylen && iv.w == t) ? 1.f : 0.f;
        *(float4*)(o + s) = ov;
    }
}

// ---------------------------------------------------------------------------
// loss + durations tail
__global__ __launch_bounds__(256) void loss_kernel(const float* __restrict__ pred,
                                                   const int* __restrict__ xl,
                                                   float* __restrict__ out,
                                                   int write_tail) {
    __shared__ float red[256];
    int tid = threadIdx.x;
    float s = 0.f;
    for (int i = tid; i < BB * TXX; i += 256) {
        int b = i / TXX, t = i - b * TXX;
        float dur = g_dur[i];
        float tl = (t < xl[b]) ? logf(dur + 1e-8f) : 0.0f;
        float d = pred[i] - tl;
        s += d * d;
        if (write_tail) out[ATTN_SZ + 1 + i] = dur;
    }
    red[tid] = s;
    __syncthreads();
    for (int off = 128; off > 0; off >>= 1) {
        if (tid < off) red[tid] += red[tid + off];
        __syncthreads();
    }
    if (tid == 0 && write_tail) {
        int sx = 0;
        for (int bb2 = 0; bb2 < BB; ++bb2) sx += xl[bb2];
        out[ATTN_SZ] = red[0] / (float)sx;
    }
}

// ---------------------------------------------------------------------------
extern "C" void kernel_launch(void* const* d_in, const int* in_sizes, int n_in,
                              void* d_out, int out_size) {
    const float* x    = (const float*)d_in[0];
    const float* y    = (const float*)d_in[1];
    const int*   xlen = (const int*)d_in[4];
    const int*   ylen = (const int*)d_in[5];
    const float* pred = (const float*)d_in[6];
    const float* W    = (const float*)d_in[7];
    const float* bias = (const float*)d_in[8];
    float* out = (float*)d_out;

    int dp_smem = DSLOT * TXX * (int)sizeof(float) +
                  (TYY + 8) * 32 * (int)sizeof(unsigned short);

    cudaFuncSetAttribute(cross_kernel, cudaFuncAttributeMaxDynamicSharedMemorySize,
                         2 * 80 * 128 * (int)sizeof(float));
    cudaFuncSetAttribute(dp_kernel, cudaFuncAttributeMaxDynamicSharedMemorySize,
                         dp_smem);

    ysq_kernel<<<dim3(TYY / 256, BB), 256>>>(y);
    xp_kernel<<<dim3(TXX / 128, BB), 160>>>(x, W, bias);
    cross_kernel<<<dim3(TXX / 128, TYY / 128, BB), 256,
                   2 * 80 * 128 * sizeof(float)>>>(y, xlen, ylen);
    dp_kernel<<<BB, 32, dp_smem>>>(xlen, ylen);
    attn_kernel<<<dim3(TXX, BB), 128>>>(ylen, out);

    int write_tail = ((size_t)out_size >= ATTN_SZ + 1 + BB * TXX) ? 1 : 0;
    loss_kernel<<<1, 256>>>(pred, xlen, out, write_tail);
}

// round 8
// speedup vs baseline: 1.3552x; 1.0932x over previous
#include <cuda_runtime.h>
#include <stdint.h>
#include <math.h>

#define BB 32
#define TXX 384
#define TYY 1536
#define DIMK 256
#define NF 80
#define NEGF (-1000000000.0f)
#define CONSTF (-73.51508265637381f)   /* -0.5*log(2*pi)*80 */

#define ATTN_SZ ((size_t)BB * TXX * TYY)

// DP ring: 32 rows = 4 blocks of 8 rows
#define DSLOT 32
#define BLK_BYTES (8 * TXX * 4)   /* 12288 */
#define MBAR_OFF (DSLOT * TXX * 4 + (TYY + 8) * 32 * 2)   /* 147968 */

// ---------------- scratch (static device memory; no allocation) -------------
__device__ float g_xp[(size_t)BB * NF * TXX];          // [b][f][t]
__device__ float g_xsq[BB * TXX];
__device__ float g_ysq[BB * TYY];
__device__ float g_v[(size_t)BB * TYY * TXX];          // [b][y][t]
__device__ int   g_idx[BB * TYY];
__device__ float g_dur[BB * TXX];

// ---------------------------------------------------------------------------
// y_square[b][s] = -0.5 * sum_f y[b][f][s]^2
__global__ void ysq_kernel(const float* __restrict__ y) {
    int b = blockIdx.y;
    int s = blockIdx.x * 256 + threadIdx.x;
    if (s >= TYY) return;
    const float* yb = y + (size_t)b * NF * TYY + s;
    float sum = 0.f;
#pragma unroll
    for (int f = 0; f < NF; ++f) {
        float v = yb[(size_t)f * TYY];
        sum += v * v;
    }
    g_ysq[b * TYY + s] = -0.5f * sum;
}

// ---------------------------------------------------------------------------
// xp[b][f][t] = sum_d x[b][t][d] * W[f][d] + bias[f];  xsq[b][t] = -0.5*sum_f xp^2
__global__ __launch_bounds__(160) void xp_kernel(const float* __restrict__ x,
                                                 const float* __restrict__ W,
                                                 const float* __restrict__ bias) {
    __shared__ float xs[32][128];   // [k][t]
    __shared__ float ws[32][80];    // [k][f]
    __shared__ float part[10][128];

    int b  = blockIdx.y;
    int t0 = blockIdx.x * 128;
    int tid = threadIdx.x;
    int tx = tid & 15;        // t-group
    int fg = tid >> 4;        // f-group (0..9)

    float acc[8][8];
#pragma unroll
    for (int i = 0; i < 8; ++i)
#pragma unroll
        for (int j = 0; j < 8; ++j) acc[i][j] = 0.f;

    const float* xb = x + ((size_t)b * TXX + t0) * DIMK;

    for (int k0 = 0; k0 < DIMK; k0 += 32) {
        for (int i = tid; i < 1024; i += 160) {     // 128 t x 8 float4
            int t = i >> 3, kq = i & 7;
            float4 v = *(const float4*)(xb + (size_t)t * DIMK + k0 + kq * 4);
            xs[kq * 4 + 0][t] = v.x; xs[kq * 4 + 1][t] = v.y;
            xs[kq * 4 + 2][t] = v.z; xs[kq * 4 + 3][t] = v.w;
        }
        for (int i = tid; i < 640; i += 160) {      // 80 f x 8 float4
            int f = i >> 3, kq = i & 7;
            float4 v = *(const float4*)(W + (size_t)f * DIMK + k0 + kq * 4);
            ws[kq * 4 + 0][f] = v.x; ws[kq * 4 + 1][f] = v.y;
            ws[kq * 4 + 2][f] = v.z; ws[kq * 4 + 3][f] = v.w;
        }
        __syncthreads();
#pragma unroll 8
        for (int kk = 0; kk < 32; ++kk) {
            float4 xa = *(const float4*)&xs[kk][tx * 8];
            float4 xb4 = *(const float4*)&xs[kk][tx * 8 + 4];
            float4 wa = *(const float4*)&ws[kk][fg * 8];
            float4 wb4 = *(const float4*)&ws[kk][fg * 8 + 4];
            float xv[8] = {xa.x, xa.y, xa.z, xa.w, xb4.x, xb4.y, xb4.z, xb4.w};
            float wv[8] = {wa.x, wa.y, wa.z, wa.w, wb4.x, wb4.y, wb4.z, wb4.w};
#pragma unroll
            for (int i = 0; i < 8; ++i)
#pragma unroll
                for (int j = 0; j < 8; ++j) acc[i][j] += xv[i] * wv[j];
        }
        __syncthreads();
    }

    float bv[8];
#pragma unroll
    for (int j = 0; j < 8; ++j) bv[j] = bias[fg * 8 + j];

    float ss[8];
#pragma unroll
    for (int i = 0; i < 8; ++i) ss[i] = 0.f;

#pragma unroll
    for (int i = 0; i < 8; ++i) {
        int t = t0 + tx * 8 + i;
#pragma unroll
        for (int j = 0; j < 8; ++j) {
            float v = acc[i][j] + bv[j];
            g_xp[((size_t)b * NF + fg * 8 + j) * TXX + t] = v;
            ss[i] += v * v;
        }
    }
#pragma unroll
    for (int i = 0; i < 8; ++i) part[fg][tx * 8 + i] = ss[i];
    __syncthreads();
    if (tid < 128) {
        float s = 0.f;
#pragma unroll
        for (int g = 0; g < 10; ++g) s += part[g][tid];
        g_xsq[b * TXX + t0 + tid] = -0.5f * s;
    }
}

// ---------------------------------------------------------------------------
// v[b][y][t] = ysq[y] + sum_f xp[b][f][t]*y[b][f][y] + xsq[t] + CONST  (masked)
// Packed f32x2 FMA inner loop.  Tiles with t0 >= xlen or t0 > y0+128 skipped:
// no finite DP path reaches t > y+1, and columns >= xlen are never consulted
// (q flows left->right only), so zeros left in g_v there are harmless.
__global__ __launch_bounds__(256) void cross_kernel(const float* __restrict__ y,
                                                    const int* __restrict__ xl,
                                                    const int* __restrict__ yl) {
    extern __shared__ float sm[];
    float* Ys = sm;            // [80][128]
    float* Xs = sm + 80 * 128; // [80][128]

    int b  = blockIdx.z;
    int y0 = blockIdx.y * 128;
    int t0 = blockIdx.x * 128;
    int ylen = yl[b], xlen = xl[b];
    if (y0 >= ylen) return;
    if (t0 >= xlen) return;
    if (t0 > y0 + 128) return;

    int tid = threadIdx.x;

    const float* yb = y + (size_t)b * NF * TYY;
    for (int i = tid; i < 2560; i += 256) {
        int f = i >> 5, q = i & 31;
        *(float4*)&Ys[f * 128 + q * 4] =
            *(const float4*)(yb + (size_t)f * TYY + y0 + q * 4);
    }
    const float* xpb = g_xp + (size_t)b * NF * TXX;
    for (int i = tid; i < 2560; i += 256) {
        int f = i >> 5, q = i & 31;
        *(float4*)&Xs[f * 128 + q * 4] =
            *(const float4*)(xpb + (size_t)f * TXX + t0 + q * 4);
    }
    __syncthreads();

    int tx = tid & 15;   // t
    int ty = tid >> 4;   // y

    unsigned long long acc2[8][4];
#pragma unroll
    for (int i = 0; i < 8; ++i)
#pragma unroll
        for (int j = 0; j < 4; ++j) acc2[i][j] = 0ull;

#pragma unroll 4
    for (int f = 0; f < NF; ++f) {
        float4 ya = *(const float4*)&Ys[f * 128 + ty * 8];
        float4 yb4 = *(const float4*)&Ys[f * 128 + ty * 8 + 4];
        float4 xa = *(const float4*)&Xs[f * 128 + tx * 8];
        float4 xb4 = *(const float4*)&Xs[f * 128 + tx * 8 + 4];
        unsigned long long xp0, xp1, xp2, xp3;
        asm("mov.b64 %0,{%1,%2};" : "=l"(xp0) : "f"(xa.x),  "f"(xa.y));
        asm("mov.b64 %0,{%1,%2};" : "=l"(xp1) : "f"(xa.z),  "f"(xa.w));
        asm("mov.b64 %0,{%1,%2};" : "=l"(xp2) : "f"(xb4.x), "f"(xb4.y));
        asm("mov.b64 %0,{%1,%2};" : "=l"(xp3) : "f"(xb4.z), "f"(xb4.w));
        float yv[8] = {ya.x, ya.y, ya.z, ya.w, yb4.x, yb4.y, yb4.z, yb4.w};
#pragma unroll
        for (int i = 0; i < 8; ++i) {
            unsigned long long yd;
            asm("mov.b64 %0,{%1,%1};" : "=l"(yd) : "f"(yv[i]));
            asm("fma.rn.f32x2 %0,%1,%2,%0;" : "+l"(acc2[i][0]) : "l"(yd), "l"(xp0));
            asm("fma.rn.f32x2 %0,%1,%2,%0;" : "+l"(acc2[i][1]) : "l"(yd), "l"(xp1));
            asm("fma.rn.f32x2 %0,%1,%2,%0;" : "+l"(acc2[i][2]) : "l"(yd), "l"(xp2));
            asm("fma.rn.f32x2 %0,%1,%2,%0;" : "+l"(acc2[i][3]) : "l"(yd), "l"(xp3));
        }
    }

    int tbase = t0 + tx * 8;
    float xsqv[8];
#pragma unroll
    for (int j = 0; j < 8; ++j) xsqv[j] = g_xsq[b * TXX + tbase + j];

#pragma unroll
    for (int i = 0; i < 8; ++i) {
        int yg = y0 + ty * 8 + i;
        if (yg >= ylen) continue;
        float ysv = g_ysq[b * TYY + yg];
        float av[8];
#pragma unroll
        for (int j2 = 0; j2 < 4; ++j2) {
            float lo, hi;
            asm("mov.b64 {%0,%1}, %2;" : "=f"(lo), "=f"(hi) : "l"(acc2[i][j2]));
            av[j2 * 2] = lo; av[j2 * 2 + 1] = hi;
        }
        float ov[8];
#pragma unroll
        for (int j = 0; j < 8; ++j) {
            float val = ((ysv + av[j]) + xsqv[j]) + CONSTF;
            ov[j] = (tbase + j < xlen) ? val : NEGF;
        }
        float* vout = g_v + ((size_t)b * TYY + yg) * TXX + tbase;
        *(float4*)(vout + 0) = make_float4(ov[0], ov[1], ov[2], ov[3]);
        *(float4*)(vout + 4) = make_float4(ov[4], ov[5], ov[6], ov[7]);
    }
}

// ---------------------------------------------------------------------------
// DP forward + backtrack.  One warp per batch.  Lane L owns t = 12L + j.
// Forward: 8-row blocks fetched with ONE cp.async.bulk (12288B) + mbarrier
// per block -> removes the 24 LDGSTS-issue-cycles/row of the per-lane path.
__global__ __launch_bounds__(32) void dp_kernel(const int* __restrict__ xl,
                                                const int* __restrict__ yl) {
    extern __shared__ float smf[];
    float* ring = smf;                                        // [DSLOT][TXX]
    unsigned short* sdec = (unsigned short*)(smf + DSLOT * TXX); // [TYY+8][32]

    int b = blockIdx.x;
    int lane = threadIdx.x;
    int ylen = yl[b], xlen = xl[b];

    const float* vb = g_v + (size_t)b * TYY * TXX;
    uint32_t ring_base = (uint32_t)__cvta_generic_to_shared(ring);
    uint32_t mbar_addr = ring_base + MBAR_OFF;

    if (lane == 0) {
#pragma unroll
        for (int m = 0; m < 4; ++m)
            asm volatile("mbarrier.init.shared.b64 [%0], 1;"
                         :: "r"(mbar_addr + m * 8) : "memory");
    }
    __syncwarp();
    asm volatile("fence.proxy.async.shared::cta;" ::: "memory");

    // issue one 8-row block via bulk copy (lane 0)
#define DP_ISSUE(bi_)                                                          \
    do {                                                                       \
        if (lane == 0) {                                                       \
            int r0_ = (bi_) * 8;                                               \
            if (r0_ + 8 > TYY) r0_ = TYY - 8;                                  \
            uint32_t mb_ = mbar_addr + ((bi_) & 3) * 8;                        \
            uint32_t dst_ = ring_base + (uint32_t)(((bi_) & 3) * BLK_BYTES);   \
            const float* src_ = vb + (size_t)r0_ * TXX;                        \
            asm volatile("mbarrier.arrive.expect_tx.shared.b64 _, [%0], %1;"   \
                         :: "r"(mb_), "r"((uint32_t)BLK_BYTES) : "memory");    \
            asm volatile(                                                      \
                "cp.async.bulk.shared::cta.global.mbarrier::complete_tx::bytes"\
                " [%0], [%1], %2, [%3];"                                       \
                :: "r"(dst_), "l"(src_), "r"((uint32_t)BLK_BYTES), "r"(mb_)    \
                : "memory");                                                   \
        }                                                                      \
    } while (0)

#define DP_WAIT(bi_)                                                           \
    do {                                                                       \
        uint32_t mb_ = mbar_addr + ((bi_) & 3) * 8;                            \
        uint32_t par_ = (uint32_t)(((bi_) >> 2) & 1);                          \
        uint32_t done_;                                                        \
        asm volatile(                                                          \
            "{\n\t.reg .pred p;\n\t"                                           \
            "mbarrier.try_wait.parity.acquire.cta.shared::cta.b64 p, [%1], %2;\n\t" \
            "selp.b32 %0,1,0,p;\n\t}"                                          \
            : "=r"(done_) : "r"(mb_), "r"(par_) : "memory");                   \
        if (!done_) {                                                          \
            asm volatile(                                                      \
                "{\n\t.reg .pred P1;\n\t"                                      \
                "WL%=:\n\t"                                                    \
                "mbarrier.try_wait.parity.acquire.cta.shared::cta.b64 P1, [%0], %1, 0x989680;\n\t" \
                "@P1 bra.uni WD%=;\n\t"                                        \
                "bra.uni WL%=;\n\t"                                            \
                "WD%=:\n\t}"                                                   \
                :: "r"(mb_), "r"(par_) : "memory");                            \
        }                                                                      \
    } while (0)

    DP_ISSUE(0);
    DP_ISSUE(1);

    float q[12];
#pragma unroll
    for (int j = 0; j < 12; ++j) q[j] = NEGF;
    if (lane == 0) q[0] = 0.0f;

    for (int yb = 0; yb < ylen; yb += 8) {
        int bi = yb >> 3;
        DP_ISSUE(bi + 2);
        DP_WAIT(bi);

#pragma unroll
        for (int h = 0; h < 2; ++h) {
            float4 r0[4], r1[4], r2[4];
#pragma unroll
            for (int k = 0; k < 4; ++k) {
                const float4* rp = (const float4*)(ring +
                    ((yb + h * 4 + k) & (DSLOT - 1)) * TXX + lane * 12);
                r0[k] = rp[0]; r1[k] = rp[1]; r2[k] = rp[2];
            }
#pragma unroll
            for (int k = 0; k < 4; ++k) {
                int yy = yb + h * 4 + k;
                float carry = __shfl_up_sync(0xffffffffu, q[11], 1);
                if (lane == 0) carry = NEGF;
                float vv[12] = {r0[k].x, r0[k].y, r0[k].z, r0[k].w,
                                r1[k].x, r1[k].y, r1[k].z, r1[k].w,
                                r2[k].x, r2[k].y, r2[k].z, r2[k].w};
                unsigned bits = 0u;
#pragma unroll
                for (int j = 11; j >= 1; --j)
                    bits |= ((q[j] < q[j - 1]) ? 1u : 0u) << j;
                bits |= (q[0] < carry) ? 1u : 0u;
#pragma unroll
                for (int j = 11; j >= 1; --j)
                    q[j] = vv[j] + fmaxf(q[j], q[j - 1]);
                q[0] = vv[0] + fmaxf(q[0], carry);
                sdec[yy * 32 + lane] = (unsigned short)bits;
            }
        }
    }
    // drain outstanding blocks so no bulk copy is in flight at exit
    {
        int bl = (ylen - 1) >> 3;
        DP_WAIT(bl + 1);
        DP_WAIT(bl + 2);
    }
    __syncwarp();

#pragma unroll
    for (int j = 0; j < 12; ++j) g_dur[b * TXX + lane * 12 + j] = 0.0f;
    __syncwarp();

    // --------- backtrack: lane-0 scalar, 8-row batched word loads ----------
    if (lane == 0) {
        int idx = xlen - 1;
        int w = idx / 12, r = idx - w * 12;
        int cnt = 0;
        int* gi = g_idx + b * TYY;
        int yy = ylen - 1;
        while (yy >= 0) {
            int w0 = w;
            unsigned wa[8], wb2[8];
            if (yy >= 7) {
#pragma unroll
                for (int k = 0; k < 8; ++k)
                    wa[k] = (unsigned)sdec[(yy - k) * 32 + w0];
                if (w0 > 0) {
#pragma unroll
                    for (int k = 0; k < 8; ++k)
                        wb2[k] = (unsigned)sdec[(yy - k) * 32 + (w0 - 1)];
                } else {
#pragma unroll
                    for (int k = 0; k < 8; ++k) wb2[k] = 0u;
                }
#pragma unroll
                for (int k = 0; k < 8; ++k) {
                    int row = yy - k;
                    unsigned use = (w == w0) ? wa[k] : wb2[k];
                    gi[row] = idx;
                    cnt++;
                    bool move = (idx != 0) && (row > 0) &&
                                ((idx == row) || (((use >> r) & 1u) != 0u));
                    if (move) {
                        g_dur[b * TXX + idx] = (float)cnt;
                        cnt = 0; idx--;
                        if (--r < 0) { r = 11; w--; }
                    }
                }
                yy -= 8;
            } else {
                int row = yy;
                unsigned use = (unsigned)sdec[row * 32 + w];
                gi[row] = idx;
                cnt++;
                bool move = (idx != 0) && (row > 0) &&
                            ((idx == row) || (((use >> r) & 1u) != 0u));
                if (move) {
                    g_dur[b * TXX + idx] = (float)cnt;
                    cnt = 0; idx--;
                    if (--r < 0) { r = 11; w--; }
                }
                yy -= 1;
            }
        }
        g_dur[b * TXX + idx] = (float)cnt;
    }
}

// ---------------------------------------------------------------------------
// attn[b][t][s] = (s < ylen && g_idx[b][s] == t) ? 1 : 0
__global__ __launch_bounds__(128) void attn_kernel(const int* __restrict__ yl,
                                                   float* __restrict__ out) {
    int b = blockIdx.y;
    int t = blockIdx.x;
    int tid = threadIdx.x;
    int ylen = yl[b];
    const int* gi = g_idx + b * TYY;
    float* o = out + ((size_t)b * TXX + t) * TYY;
#pragma unroll
    for (int it = 0; it < 3; ++it) {
        int s4 = tid + it * 128;
        int s = s4 * 4;
        int4 iv = *(const int4*)(gi + s);
        float4 ov;
        ov.x = (s + 0 < ylen && iv.x == t) ? 1.f : 0.f;
        ov.y = (s + 1 < ylen && iv.y == t) ? 1.f : 0.f;
        ov.z = (s + 2 < ylen && iv.z == t) ? 1.f : 0.f;
        ov.w = (s + 3 < ylen && iv.w == t) ? 1.f : 0.f;
        *(float4*)(o + s) = ov;
    }
}

// ---------------------------------------------------------------------------
// loss + durations tail
__global__ __launch_bounds__(256) void loss_kernel(const float* __restrict__ pred,
                                                   const int* __restrict__ xl,
                                                   float* __restrict__ out,
                                                   int write_tail) {
    __shared__ float red[256];
    int tid = threadIdx.x;
    float s = 0.f;
    for (int i = tid; i < BB * TXX; i += 256) {
        int b = i / TXX, t = i - b * TXX;
        float dur = g_dur[i];
        float tl = (t < xl[b]) ? logf(dur + 1e-8f) : 0.0f;
        float d = pred[i] - tl;
        s += d * d;
        if (write_tail) out[ATTN_SZ + 1 + i] = dur;
    }
    red[tid] = s;
    __syncthreads();
    for (int off = 128; off > 0; off >>= 1) {
        if (tid < off) red[tid] += red[tid + off];
        __syncthreads();
    }
    if (tid == 0 && write_tail) {
        int sx = 0;
        for (int bb2 = 0; bb2 < BB; ++bb2) sx += xl[bb2];
        out[ATTN_SZ] = red[0] / (float)sx;
    }
}

// ---------------------------------------------------------------------------
extern "C" void kernel_launch(void* const* d_in, const int* in_sizes, int n_in,
                              void* d_out, int out_size) {
    const float* x    = (const float*)d_in[0];
    const float* y    = (const float*)d_in[1];
    const int*   xlen = (const int*)d_in[4];
    const int*   ylen = (const int*)d_in[5];
    const float* pred = (const float*)d_in[6];
    const float* W    = (const float*)d_in[7];
    const float* bias = (const float*)d_in[8];
    float* out = (float*)d_out;

    int dp_smem = MBAR_OFF + 32;   // ring + sdec + 4 mbarriers

    cudaFuncSetAttribute(cross_kernel, cudaFuncAttributeMaxDynamicSharedMemorySize,
                         2 * 80 * 128 * (int)sizeof(float));
    cudaFuncSetAttribute(dp_kernel, cudaFuncAttributeMaxDynamicSharedMemorySize,
                         dp_smem);

    ysq_kernel<<<dim3(TYY / 256, BB), 256>>>(y);
    xp_kernel<<<dim3(TXX / 128, BB), 160>>>(x, W, bias);
    cross_kernel<<<dim3(TXX / 128, TYY / 128, BB), 256,
                   2 * 80 * 128 * sizeof(float)>>>(y, xlen, ylen);
    dp_kernel<<<BB, 32, dp_smem>>>(xlen, ylen);
    attn_kernel<<<dim3(TXX, BB), 128>>>(ylen, out);

    int write_tail = ((size_t)out_size >= ATTN_SZ + 1 + BB * TXX) ? 1 : 0;
    loss_kernel<<<1, 256>>>(pred, xlen, out, write_tail);
}